// round 14
// baseline (speedup 1.0000x reference)
#include <cuda_runtime.h>
#include <cstdint>

// Shapes (fixed by the problem)
#define D_MODEL   1024
#define HEAD_DIM  64
#define NUM_HEADS 16
#define BATCH     8
#define SEQ       4096
#define KSLICES   32          // K-split for the V GEMV (phase 1)

#define NPROLOG   256         // prologue CTAs (2 per SM, all co-resident)

// Scratch + sync (allocation-free rule: __device__ globals).
// Data buffers fully overwritten each replay; counters reset by last arriver.
__device__ float g_Vpart[KSLICES * BATCH * HEAD_DIM];
__device__ float g_row[BATCH * D_MODEL];
__device__ int   g_cnt1 = 0;   // phase-1 arrivals (target NPROLOG)
__device__ int   g_cnt2 = 0;   // phase-2 arrivals (target NPROLOG)

// ---------------------------------------------------------------------------
// Kernel 1 (fused prologue), grid = 256 CTAs x 256 threads:
//  Phase 1: g_Vpart[ks][b][d] = sum_{i in slice} value[b,i]*Wv[i,d]
//           + distributed g_row[b,j] = bo[j] reset.
//  Gate   : counter barrier (256 CTAs, 2/SM, guaranteed co-resident).
//  Phase 2: g_row[b,j] += sum_{ii in quarter} V[b,ii]*Wo[(h*64+ii)*1024+j].
//           Wo (4 MB) read exactly once, spread over 256 CTAs.
// ---------------------------------------------------------------------------
__global__ __launch_bounds__(256, 2)
void prologue_fused_kernel(const float* __restrict__ value,
                           const float* __restrict__ Wv,
                           const float* __restrict__ bv,
                           const float* __restrict__ Wo,
                           const float* __restrict__ bo) {
    const int bid = blockIdx.x;           // 0..255
    const int t   = threadIdx.x;          // 0..255

    __shared__ float red[4][HEAD_DIM];
    __shared__ float sV[BATCH * HEAD_DIM];

    // ---- Phase 1 ---------------------------------------------------------
    // g_row reset: first 32 CTAs cover the 8192 elements.
    const int gid = bid * 256 + t;
    if (gid < BATCH * D_MODEL)
        g_row[gid] = bo[gid & (D_MODEL - 1)];

    {
        const int ks  = bid & (KSLICES - 1);   // 0..31
        const int b   = bid >> 5;              // 0..7
        const int d   = t & (HEAD_DIM - 1);    // 0..63
        const int sub = t >> 6;                // 0..3
        const int i0  = ks * (D_MODEL / KSLICES) + sub * (D_MODEL / KSLICES / 4);
        const float* vrow = value + b * D_MODEL;

        float acc = 0.f;
        #pragma unroll
        for (int i = 0; i < D_MODEL / KSLICES / 4; ++i) {   // 8 iters
            const int ii = i0 + i;
            acc += vrow[ii] * Wv[ii * HEAD_DIM + d];
        }
        red[sub][d] = acc;
        __syncthreads();
        if (sub == 0) {
            g_Vpart[(ks * BATCH + b) * HEAD_DIM + d] =
                red[0][d] + red[1][d] + red[2][d] + red[3][d];
        }
    }
    __syncthreads();
    if (t == 0) { __threadfence(); atomicAdd(&g_cnt1, 1); }

    // ---- Gate (all 256 CTAs resident at 2/SM -> cannot deadlock) ---------
    if (t == 0) {
        volatile int* p = &g_cnt1;
        while (*p < NPROLOG) __nanosleep(64);
        __threadfence();
    }
    __syncthreads();

    // ---- Phase 2 ---------------------------------------------------------
    {
        const int j       = (bid & 3) * 256 + t;           // 0..1023
        const int h       = (bid >> 2) & (NUM_HEADS - 1);  // 0..15
        const int quarter = bid >> 6;                      // 0..3

        #pragma unroll
        for (int e = t; e < BATCH * HEAD_DIM; e += 256) {
            const int d2 = e & (HEAD_DIM - 1);
            float s = bv[d2];
            #pragma unroll
            for (int kk = 0; kk < KSLICES; ++kk)
                s += g_Vpart[kk * BATCH * HEAD_DIM + e];
            sV[e] = s;
        }
        __syncthreads();

        float accb[BATCH];
        #pragma unroll
        for (int b2 = 0; b2 < BATCH; ++b2) accb[b2] = 0.f;

        const int ii0 = quarter * (HEAD_DIM / 4);
        const float* wcol = Wo + ((size_t)h * HEAD_DIM + ii0) * D_MODEL + j;
        #pragma unroll
        for (int ii = 0; ii < HEAD_DIM / 4; ++ii) {        // 16 coalesced loads
            const float w = wcol[(size_t)ii * D_MODEL];
            const float* vv = sV + ii0 + ii;
            #pragma unroll
            for (int b2 = 0; b2 < BATCH; ++b2)
                accb[b2] += vv[b2 * HEAD_DIM] * w;         // smem broadcast
        }
        #pragma unroll
        for (int b2 = 0; b2 < BATCH; ++b2)
            atomicAdd(&g_row[b2 * D_MODEL + j], accb[b2]);
    }

    // ---- Counter reset for next replay (last arriver) --------------------
    __syncthreads();
    if (t == 0) {
        __threadfence();
        if (atomicAdd(&g_cnt2, 1) == NPROLOG - 1) {
            g_cnt1 = 0;
            __threadfence();
            g_cnt2 = 0;
        }
    }
}

// ---------------------------------------------------------------------------
// Kernel 2: out[b,s,:] = row[b,:] via bulk-async DMA stores.
// Each CTA stages its batch row (4 KB) in SMEM once, then one thread issues
// 32 cp.async.bulk shared->global copies of 4 KB each. This bypasses the
// per-STG.128 LSU/L1 issue cost that capped R13 at 21 us (L1=61.6%).
// ---------------------------------------------------------------------------
#define S_PER_BLOCK 32
#define ROW_BYTES   (D_MODEL * 4)   // 4096

__global__ __launch_bounds__(256, 8)
void broadcast_bulk_kernel(float* __restrict__ out) {
    __shared__ alignas(128) float srow[D_MODEL];   // 4 KB

    const int b  = blockIdx.y;
    const int s0 = blockIdx.x * S_PER_BLOCK;
    const int t  = threadIdx.x;

    // Stage the row in SMEM (one float4 per thread).
    reinterpret_cast<float4*>(srow)[t] =
        reinterpret_cast<const float4*>(g_row)[b * (D_MODEL / 4) + t];
    __syncthreads();
    // Order generic-proxy SMEM writes before async-proxy bulk reads.
    asm volatile("fence.proxy.async.shared::cta;" ::: "memory");

    if (t == 0) {
        uint32_t saddr = (uint32_t)__cvta_generic_to_shared(srow);
        float* dst0 = out + ((size_t)b * SEQ + s0) * D_MODEL;
        #pragma unroll
        for (int s = 0; s < S_PER_BLOCK; ++s) {
            asm volatile(
                "cp.async.bulk.global.shared::cta.bulk_group [%0], [%1], %2;"
                :: "l"(dst0 + (size_t)s * D_MODEL), "r"(saddr), "n"(ROW_BYTES)
                : "memory");
        }
        asm volatile("cp.async.bulk.commit_group;" ::: "memory");
        asm volatile("cp.async.bulk.wait_group 0;" ::: "memory");
    }
}

// ---------------------------------------------------------------------------
// Inputs (metadata order): 0 query, 1 key, 2 value, 3 Wq, 4 bq,
//                          5 Wk, 6 bk, 7 Wv, 8 bv, 9 Wo, 10 bo
// softmax over kv_len=1 is identically 1 -> query/key/Wq/bq/Wk/bk are dead.
// ---------------------------------------------------------------------------
extern "C" void kernel_launch(void* const* d_in, const int* in_sizes, int n_in,
                              void* d_out, int out_size) {
    const float* value = (const float*)d_in[2];
    const float* Wv    = (const float*)d_in[7];
    const float* bv    = (const float*)d_in[8];
    const float* Wo    = (const float*)d_in[9];
    const float* bo    = (const float*)d_in[10];
    float* out = (float*)d_out;

    prologue_fused_kernel<<<NPROLOG, 256>>>(value, Wv, bv, Wo, bo);

    dim3 gridC(SEQ / S_PER_BLOCK, BATCH);
    broadcast_bulk_kernel<<<gridC, 256>>>(out);
}

// round 15
// speedup vs baseline: 1.0831x; 1.0831x over previous
#include <cuda_runtime.h>
#include <cstdint>

// Shapes (fixed by the problem)
#define D_MODEL   1024
#define HEAD_DIM  64
#define NUM_HEADS 16
#define BATCH     8
#define SEQ       4096
#define KSLICES   16          // K-split for the V GEMV (phase 1)

#define NPROLOG   128         // prologue CTAs (one per SM, all co-resident)

// Scratch + sync (allocation-free rule: __device__ globals).
// Data buffers fully overwritten each replay; counters reset by last arriver.
__device__ float g_Vpart[KSLICES * BATCH * HEAD_DIM];
__device__ float g_row[BATCH * D_MODEL];
__device__ int   g_cnt1 = 0;   // phase-1 arrivals (target NPROLOG)
__device__ int   g_cnt2 = 0;   // phase-2 arrivals (target NPROLOG)

// ---------------------------------------------------------------------------
// Kernel 1 (fused prologue), grid = 128 CTAs x 256 threads (R13-proven):
//  Phase 1: g_Vpart[ks][b][d] = sum_{i in slice} value[b,i]*Wv[i,d]
//           + distributed g_row[b,j] = bo[j] reset.
//  Gate   : counter barrier across the 128 CTAs (one per SM -> co-resident).
//  Phase 2: g_row[b,j] += sum_{ii in half} V[b,ii]*Wo[(h*64+ii)*1024+j].
//  Ends with griddepcontrol.launch_dependents (PDL hand-off to broadcast).
// ---------------------------------------------------------------------------
__global__ __launch_bounds__(256, 1)
void prologue_fused_kernel(const float* __restrict__ value,
                           const float* __restrict__ Wv,
                           const float* __restrict__ bv,
                           const float* __restrict__ Wo,
                           const float* __restrict__ bo) {
    const int bid = blockIdx.x;           // 0..127
    const int t   = threadIdx.x;          // 0..255

    __shared__ float red[4][HEAD_DIM];
    __shared__ float sV[BATCH * HEAD_DIM];

    // ---- Phase 1 ---------------------------------------------------------
    // g_row reset: 128*256 = 32768 threads cover 8192 elements.
    const int gid = bid * 256 + t;
    if (gid < BATCH * D_MODEL)
        g_row[gid] = bo[gid & (D_MODEL - 1)];

    {
        const int ks  = bid & (KSLICES - 1);   // 0..15
        const int b   = bid >> 4;              // 0..7
        const int d   = t & (HEAD_DIM - 1);    // 0..63
        const int sub = t >> 6;                // 0..3
        const int i0  = ks * (D_MODEL / KSLICES) + sub * (D_MODEL / KSLICES / 4);
        const float* vrow = value + b * D_MODEL;

        float acc = 0.f;
        #pragma unroll
        for (int i = 0; i < D_MODEL / KSLICES / 4; ++i) {   // 16 iters, full MLP
            const int ii = i0 + i;
            acc += vrow[ii] * Wv[ii * HEAD_DIM + d];
        }
        red[sub][d] = acc;
        __syncthreads();
        if (sub == 0) {
            g_Vpart[(ks * BATCH + b) * HEAD_DIM + d] =
                red[0][d] + red[1][d] + red[2][d] + red[3][d];
        }
    }
    __syncthreads();
    if (t == 0) { __threadfence(); atomicAdd(&g_cnt1, 1); }

    // ---- Gate (128 CTAs, one per SM -> cannot deadlock) ------------------
    if (t == 0) {
        volatile int* p = &g_cnt1;
        while (*p < NPROLOG) __nanosleep(64);
        __threadfence();
    }
    __syncthreads();

    // ---- Phase 2 ---------------------------------------------------------
    {
        const int j    = (bid & 3) * 256 + t;           // 0..1023
        const int h    = (bid >> 2) & (NUM_HEADS - 1);  // 0..15
        const int half = bid >> 6;                      // 0..1 -> ii split

        #pragma unroll
        for (int e = t; e < BATCH * HEAD_DIM; e += 256) {
            const int d2 = e & (HEAD_DIM - 1);
            float s = bv[d2];
            #pragma unroll
            for (int kk = 0; kk < KSLICES; ++kk)
                s += g_Vpart[kk * BATCH * HEAD_DIM + e];
            sV[e] = s;
        }
        __syncthreads();

        float accb[BATCH];
        #pragma unroll
        for (int b2 = 0; b2 < BATCH; ++b2) accb[b2] = 0.f;

        const int ii0 = half * (HEAD_DIM / 2);
        const float* wcol = Wo + ((size_t)h * HEAD_DIM + ii0) * D_MODEL + j;
        #pragma unroll
        for (int ii = 0; ii < HEAD_DIM / 2; ++ii) {     // 32 coalesced loads
            const float w = wcol[(size_t)ii * D_MODEL];
            const float* vv = sV + ii0 + ii;
            #pragma unroll
            for (int b2 = 0; b2 < BATCH; ++b2)
                accb[b2] += vv[b2 * HEAD_DIM] * w;      // smem broadcast
        }
        #pragma unroll
        for (int b2 = 0; b2 < BATCH; ++b2)
            atomicAdd(&g_row[b2 * D_MODEL + j], accb[b2]);
    }

    // ---- Counter reset for next replay (last arriver) --------------------
    __syncthreads();
    if (t == 0) {
        __threadfence();
        if (atomicAdd(&g_cnt2, 1) == NPROLOG - 1) {
            g_cnt1 = 0;
            __threadfence();
            g_cnt2 = 0;
        }
    }
    __syncthreads();

    // ---- PDL: this CTA's g_row contributions are globally visible --------
    asm volatile("griddepcontrol.launch_dependents;" ::: "memory");
}

// ---------------------------------------------------------------------------
// Kernel 2: out[b,s,:] = row[b,:]  (134 MB float4 stores; measured HBM
// write wall ~3.5 TB/s -> ~21 us floor). Launched via PDL so its 1024-CTA
// ramp overlaps the prologue; griddepcontrol.wait gates the g_row read.
// ---------------------------------------------------------------------------
#define S_PER_BLOCK 32
#define ROW_VEC4    (D_MODEL / 4)   // 256

__global__ __launch_bounds__(256, 8)
void broadcast_kernel(float4* __restrict__ out) {
    const int b  = blockIdx.y;
    const int s0 = blockIdx.x * S_PER_BLOCK;
    const int t  = threadIdx.x;

    // Block until the prologue grid has made g_row visible.
    asm volatile("griddepcontrol.wait;" ::: "memory");

    const float4 v = reinterpret_cast<const float4*>(g_row)[b * ROW_VEC4 + t];

    size_t base = ((size_t)b * SEQ + s0) * ROW_VEC4 + t;
    #pragma unroll
    for (int s = 0; s < S_PER_BLOCK; ++s) {
        out[base + (size_t)s * ROW_VEC4] = v;
    }
}

// ---------------------------------------------------------------------------
// Inputs (metadata order): 0 query, 1 key, 2 value, 3 Wq, 4 bq,
//                          5 Wk, 6 bk, 7 Wv, 8 bv, 9 Wo, 10 bo
// softmax over kv_len=1 is identically 1 -> query/key/Wq/bq/Wk/bk are dead.
// ---------------------------------------------------------------------------
extern "C" void kernel_launch(void* const* d_in, const int* in_sizes, int n_in,
                              void* d_out, int out_size) {
    const float* value = (const float*)d_in[2];
    const float* Wv    = (const float*)d_in[7];
    const float* bv    = (const float*)d_in[8];
    const float* Wo    = (const float*)d_in[9];
    const float* bo    = (const float*)d_in[10];
    float* out = (float*)d_out;

    prologue_fused_kernel<<<NPROLOG, 256>>>(value, Wv, bv, Wo, bo);

    // Broadcast launched as a programmatic dependent: spins up during the
    // prologue, blocks at griddepcontrol.wait until g_row is ready.
    cudaLaunchConfig_t cfg = {};
    cfg.gridDim  = dim3(SEQ / S_PER_BLOCK, BATCH);
    cfg.blockDim = dim3(256);
    cfg.stream   = 0;
    cudaLaunchAttribute attr[1];
    attr[0].id = cudaLaunchAttributeProgrammaticStreamSerialization;
    attr[0].val.programmaticStreamSerializationAllowed = 1;
    cfg.attrs = attr;
    cfg.numAttrs = 1;
    float4* out4 = (float4*)out;
    cudaLaunchKernelEx(&cfg, broadcast_kernel, out4);
}